// round 14
// baseline (speedup 1.0000x reference)
#include <cuda_runtime.h>
#include <math.h>

#define D 512
#define V 17
#define MAX_SEGS 64
#define EPAD 20
#define TPB 512

// Scratch (allocation-free, graph-safe).
__device__ float g_midT[D * EPAD];         // finalized gelu-mid, transposed+padded
__device__ int   g_hist[MAX_SEGS][V];      // per-segment token counts

// ---------------------------------------------------------------------------
// k1: CTAs 0..63: FULL-K GEMM1 for 8 mid-columns each -> g_midT (finalized,
//     bias + exact GELU, transposed layout). CTAs 64..: per-segment histograms.
// Single wave (128 CTAs). Triggers the dependent k2 launch as soon as each
// block's results are stored.
// ---------------------------------------------------------------------------
__global__ void __launch_bounds__(TPB, 1)
k1(const float* __restrict__ E, const float* __restrict__ W1,
   const float* __restrict__ b1, const int* __restrict__ tok,
   const int* __restrict__ cu, int n_segs) {
    __shared__ float etr[D * EPAD];        // 40960B; reused as reduction buffer
    const int bid = blockIdx.x;
    const int tid = threadIdx.x;

    if (bid < 64) {
        const int jl = tid & 7;
        const int ty = tid >> 3;           // 0..63: k-group of 8
        const int jbase = bid * 8;

        // stage E (17x512) transposed -> etr[k*EPAD+v]; 2176 float4 total
        const float4* E4 = (const float4*)E;
#pragma unroll
        for (int r = 0; r < 4; r++) {
            const int i = r * TPB + tid;
            const float4 e = E4[i];
            const int v = i >> 7;
            const int k = (i & 127) * 4;
            etr[(k + 0) * EPAD + v] = e.x;
            etr[(k + 1) * EPAD + v] = e.y;
            etr[(k + 2) * EPAD + v] = e.z;
            etr[(k + 3) * EPAD + v] = e.w;
        }
        if (tid < V * 128 - 4 * TPB) {
            const int i = 4 * TPB + tid;
            const float4 e = E4[i];
            const int v = i >> 7;
            const int k = (i & 127) * 4;
            etr[(k + 0) * EPAD + v] = e.x;
            etr[(k + 1) * EPAD + v] = e.y;
            etr[(k + 2) * EPAD + v] = e.z;
            etr[(k + 3) * EPAD + v] = e.w;
        }
        __syncthreads();

        float acc[V];
#pragma unroll
        for (int v = 0; v < V; v++) acc[v] = 0.0f;

        const float* wp = W1 + (size_t)(ty * 8) * D + jbase + jl;
        float w[8];
#pragma unroll
        for (int kk = 0; kk < 8; kk++) w[kk] = wp[kk * D];

#pragma unroll
        for (int kk = 0; kk < 8; kk++) {
            const float* er = &etr[(ty * 8 + kk) * EPAD];
            const float4 e0 = *(const float4*)(er);
            const float4 e1 = *(const float4*)(er + 4);
            const float4 e2 = *(const float4*)(er + 8);
            const float4 e3 = *(const float4*)(er + 12);
            const float  ee = er[16];
            const float  wv = w[kk];
            acc[0]  += e0.x * wv;  acc[1]  += e0.y * wv;
            acc[2]  += e0.z * wv;  acc[3]  += e0.w * wv;
            acc[4]  += e1.x * wv;  acc[5]  += e1.y * wv;
            acc[6]  += e1.z * wv;  acc[7]  += e1.w * wv;
            acc[8]  += e2.x * wv;  acc[9]  += e2.y * wv;
            acc[10] += e2.z * wv;  acc[11] += e2.w * wv;
            acc[12] += e3.x * wv;  acc[13] += e3.y * wv;
            acc[14] += e3.z * wv;  acc[15] += e3.w * wv;
            acc[16] += ee   * wv;
        }
        __syncthreads();       // done reading etr; reuse as reduction buffer

        float* red = etr;      // [64][V*8] = 8704 floats
#pragma unroll
        for (int v = 0; v < V; v++) red[ty * (V * 8) + v * 8 + jl] = acc[v];
        __syncthreads();

        if (tid < V * 8) {
            const int j = jbase + (tid & 7);
            float s = b1[j];
#pragma unroll
            for (int g = 0; g < 64; g++) s += red[g * (V * 8) + tid];
            s = 0.5f * s * (1.0f + erff(s * 0.70710678118654752f));
            g_midT[j * EPAD + (tid >> 3)] = s;
        }
        cudaTriggerProgrammaticLaunchCompletion();
        return;
    }

    // -------- histogram CTA --------
    const int s = bid - 64;
    if (s < n_segs) {
        const int start = cu[s];
        const int end = cu[s + 1];
        const int wid = tid >> 5;
        int* cnt = (int*)etr;              // 16*32 ints

        for (int i = tid; i < 16 * 32; i += TPB) cnt[i] = 0;
        __syncthreads();
        for (int base = start + tid * 4; base < end; base += TPB * 4) {
            int t0 = -1, t1 = -1, t2 = -1, t3 = -1;
            if (base + 0 < end) t0 = tok[base + 0];
            if (base + 1 < end) t1 = tok[base + 1];
            if (base + 2 < end) t2 = tok[base + 2];
            if (base + 3 < end) t3 = tok[base + 3];
            if (t0 >= 0) atomicAdd(&cnt[wid * 32 + t0], 1);
            if (t1 >= 0) atomicAdd(&cnt[wid * 32 + t1], 1);
            if (t2 >= 0) atomicAdd(&cnt[wid * 32 + t2], 1);
            if (t3 >= 0) atomicAdd(&cnt[wid * 32 + t3], 1);
        }
        __syncthreads();
        if (tid < V) {
            int c = 0;
#pragma unroll
            for (int w = 0; w < 16; w++) c += cnt[w * 32 + tid];
            g_hist[s][tid] = c;
        }
    }
    cudaTriggerProgrammaticLaunchCompletion();
}

// ---------------------------------------------------------------------------
// k2 (PDL secondary): launches while k1 runs; prefetches W2 into registers
// before the dependency sync, then stages g_midT, full-K GEMM2, mix, store.
// ---------------------------------------------------------------------------
__global__ void __launch_bounds__(TPB, 1)
k2(const float* __restrict__ W2, const float* __restrict__ b2,
   const int* __restrict__ cu, float* __restrict__ out, int n_segs) {
    __shared__ float etr[D * EPAD];
    __shared__ float Ht[V * 8 * 4];
    __shared__ float fcs[MAX_SEGS * 18];
    __shared__ float inv[MAX_SEGS];

    const int bid = blockIdx.x;
    const int tid = threadIdx.x;
    const int jl = tid & 7;
    const int ty = tid >> 3;
    const int jbase = bid * 8;

    // ---- pre-sync prelude: everything independent of k1 ----
    const float* wp = W2 + (size_t)(ty * 8) * D + jbase + jl;
    float w[8];
#pragma unroll
    for (int kk = 0; kk < 8; kk++) w[kk] = wp[kk * D];

    float b2v = 0.0f;
    if (tid < V * 8) b2v = b2[jbase + (tid & 7)];
    if (tid < n_segs) inv[tid] = 1.0f / (float)(cu[tid + 1] - cu[tid]);

    // ---- wait for k1's writes (g_midT, g_hist) to be visible ----
    cudaGridDependencySynchronize();

    // segment counts
    {
        const int i0 = tid, i1 = tid + TPB, i2 = tid + 2 * TPB;
        int c0 = 0, c1 = 0, c2 = 0;
        if (i0 < n_segs * V) c0 = ((const int*)g_hist)[i0];
        if (i1 < n_segs * V) c1 = ((const int*)g_hist)[i1];
        if (i2 < n_segs * V) c2 = ((const int*)g_hist)[i2];
        if (i0 < n_segs * V) fcs[(i0 / V) * 18 + (i0 % V)] = (float)c0;
        if (i1 < n_segs * V) fcs[(i1 / V) * 18 + (i1 % V)] = (float)c1;
        if (i2 < n_segs * V) fcs[(i2 / V) * 18 + (i2 % V)] = (float)c2;
    }

    // stage full transposed mid table: 5 fixed float4 LDG per thread
    {
        const float4* M4 = (const float4*)g_midT;
        float4* S4 = (float4*)etr;
        const float4 m0 = M4[tid];
        const float4 m1 = M4[tid + 512];
        const float4 m2 = M4[tid + 1024];
        const float4 m3 = M4[tid + 1536];
        const float4 m4 = M4[tid + 2048];
        S4[tid] = m0;  S4[tid + 512] = m1;  S4[tid + 1024] = m2;
        S4[tid + 1536] = m3;  S4[tid + 2048] = m4;
    }
    __syncthreads();

    float acc[V];
#pragma unroll
    for (int v = 0; v < V; v++) acc[v] = 0.0f;

#pragma unroll
    for (int kk = 0; kk < 8; kk++) {
        const float* er = &etr[(ty * 8 + kk) * EPAD];
        const float4 e0 = *(const float4*)(er);
        const float4 e1 = *(const float4*)(er + 4);
        const float4 e2 = *(const float4*)(er + 8);
        const float4 e3 = *(const float4*)(er + 12);
        const float  ee = er[16];
        const float  wv = w[kk];
        acc[0]  += e0.x * wv;  acc[1]  += e0.y * wv;
        acc[2]  += e0.z * wv;  acc[3]  += e0.w * wv;
        acc[4]  += e1.x * wv;  acc[5]  += e1.y * wv;
        acc[6]  += e1.z * wv;  acc[7]  += e1.w * wv;
        acc[8]  += e2.x * wv;  acc[9]  += e2.y * wv;
        acc[10] += e2.z * wv;  acc[11] += e2.w * wv;
        acc[12] += e3.x * wv;  acc[13] += e3.y * wv;
        acc[14] += e3.z * wv;  acc[15] += e3.w * wv;
        acc[16] += ee   * wv;
    }
    __syncthreads();

    float* red = etr;
#pragma unroll
    for (int v = 0; v < V; v++) red[ty * (V * 8) + v * 8 + jl] = acc[v];
    __syncthreads();

    if (tid < V * 8) {
        float s = b2v;
#pragma unroll
        for (int g = 0; g < 64; g++) s += red[g * (V * 8) + tid];
        Ht[tid] = s;
    }
    __syncthreads();

    const int s = tid >> 3;
    if (s < n_segs) {
        const float* f = &fcs[s * 18];
        float a = 0.0f;
#pragma unroll
        for (int v = 0; v < V; v++) a += f[v] * Ht[v * 8 + jl];
        out[s * D + jbase + jl] = a * inv[s];
    }
}

// ---------------------------------------------------------------------------
extern "C" void kernel_launch(void* const* d_in, const int* in_sizes, int n_in,
                              void* d_out, int out_size) {
    const int*   tok = (const int*)  d_in[0];
    const int*   cu  = (const int*)  d_in[1];
    const float* E   = (const float*)d_in[2];
    const float* W1  = (const float*)d_in[3];
    const float* b1  = (const float*)d_in[4];
    const float* W2  = (const float*)d_in[5];
    const float* b2  = (const float*)d_in[6];
    float*       out = (float*)d_out;

    int n_segs = in_sizes[1] - 1;
    if (n_segs > MAX_SEGS) n_segs = MAX_SEGS;

    k1<<<64 + n_segs, TPB>>>(E, W1, b1, tok, cu, n_segs);

    // k2 as PDL secondary: launches under k1, syncs on its completion.
    cudaLaunchConfig_t cfg = {};
    cfg.gridDim = dim3(64, 1, 1);
    cfg.blockDim = dim3(TPB, 1, 1);
    cfg.dynamicSmemBytes = 0;
    cudaLaunchAttribute attr[1];
    attr[0].id = cudaLaunchAttributeProgrammaticStreamSerialization;
    attr[0].val.programmaticStreamSerializationAllowed = 1;
    cfg.attrs = attr;
    cfg.numAttrs = 1;
    cudaLaunchKernelEx(&cfg, k2, W2, b2, cu, out, n_segs);
}